// round 17
// baseline (speedup 1.0000x reference)
#include <cuda_runtime.h>
#include <cstdint>

#define NN   100000
#define EE   1600000
#define FIN  128
#define HH   128
#define OUTC 64

// ---------------- scratch (no allocation allowed) ----------------
__device__ __align__(16) int   g_cnt[NN];
__device__ __align__(16) int   g_rowptr[NN + 1];
__device__ __align__(16) int   g_cursor[NN];
__device__ __align__(16) int   g_bsum[256];
__device__ __align__(16) int   g_csr_src[EE];
__device__ __align__(16) float g_ta[(size_t)NN * HH];         // activation buffer A
__device__ __align__(16) float g_tb[(size_t)NN * HH];         // activation buffer B
__device__ __align__(16) uint32_t g_ahi[(size_t)NN * 64];     // packed bf16 hi (kp-major)
__device__ __align__(16) uint32_t g_alo[(size_t)NN * 64];     // packed bf16 lo
__device__ __align__(16) uint32_t g_w1hi[64 * HH],   g_w1lo[64 * HH];
__device__ __align__(16) uint32_t g_w2hi[64 * HH],   g_w2lo[64 * HH];
__device__ __align__(16) uint32_t g_w3hi[64 * OUTC], g_w3lo[64 * OUTC];

// ================= bf16-split helpers =================
__device__ __forceinline__ void pack_split(float2 v, uint32_t& hi, uint32_t& lo) {
    asm("cvt.rn.bf16x2.f32 %0, %1, %2;" : "=r"(hi) : "f"(v.y), "f"(v.x));
    float h0 = __uint_as_float(hi << 16);
    float h1 = __uint_as_float(hi & 0xFFFF0000u);
    float l0 = v.x - h0;
    float l1 = v.y - h1;
    asm("cvt.rn.bf16x2.f32 %0, %1, %2;" : "=r"(lo) : "f"(l1), "f"(l0));
}
__device__ __forceinline__ void mma_bf16(float c[4], const uint32_t a[4], const uint32_t b[2]) {
    asm volatile(
        "mma.sync.aligned.m16n8k16.row.col.f32.bf16.bf16.f32 "
        "{%0,%1,%2,%3}, {%4,%5,%6,%7}, {%8,%9}, {%0,%1,%2,%3};"
        : "+f"(c[0]), "+f"(c[1]), "+f"(c[2]), "+f"(c[3])
        : "r"(a[0]), "r"(a[1]), "r"(a[2]), "r"(a[3]), "r"(b[0]), "r"(b[1]));
}
__device__ __forceinline__ float dinv_of(int i) {
    return rsqrtf(1.0f + (float)g_cnt[i]);
}

// ================= setup =================
__global__ void k_zero(const float* __restrict__ W1, const float* __restrict__ W2,
                       const float* __restrict__ W3, int n) {
    int i = blockIdx.x * blockDim.x + threadIdx.x;
    if (i < n) g_cnt[i] = 0;
    if (i < 64 * HH) {
        int kp = i / HH, nn = i % HH;
        uint32_t hi, lo;
        pack_split(make_float2(W1[(2 * kp) * HH + nn], W1[(2 * kp + 1) * HH + nn]), hi, lo);
        g_w1hi[i] = hi; g_w1lo[i] = lo;
        pack_split(make_float2(W2[(2 * kp) * HH + nn], W2[(2 * kp + 1) * HH + nn]), hi, lo);
        g_w2hi[i] = hi; g_w2lo[i] = lo;
    }
    if (i < 64 * OUTC) {
        int kp = i / OUTC, nn = i % OUTC;
        uint32_t hi, lo;
        pack_split(make_float2(W3[(2 * kp) * OUTC + nn], W3[(2 * kp + 1) * OUTC + nn]), hi, lo);
        g_w3hi[i] = hi; g_w3lo[i] = lo;
    }
}
__global__ void k_count(const int* __restrict__ dst, int e) {
    int i = blockIdx.x * blockDim.x + threadIdx.x;
    if (i < e) atomicAdd(&g_cnt[dst[i]], 1);
}
__global__ void k_scan1(int n) {
    __shared__ int sh[1024];
    int tid = threadIdx.x;
    int i = blockIdx.x * 1024 + tid;
    int v = (i < n) ? g_cnt[i] : 0;
    sh[tid] = v;
    __syncthreads();
#pragma unroll
    for (int off = 1; off < 1024; off <<= 1) {
        int t = (tid >= off) ? sh[tid - off] : 0;
        __syncthreads();
        sh[tid] += t;
        __syncthreads();
    }
    if (i < n) g_rowptr[i] = sh[tid] - v;
    if (tid == 1023) g_bsum[blockIdx.x] = sh[1023];
}
__global__ void k_scan2(int nb, int n) {
    __shared__ int sh[128];
    int tid = threadIdx.x;
    int v = (tid < nb) ? g_bsum[tid] : 0;
    sh[tid] = v;
    __syncthreads();
#pragma unroll
    for (int off = 1; off < 128; off <<= 1) {
        int t = (tid >= off) ? sh[tid - off] : 0;
        __syncthreads();
        sh[tid] += t;
        __syncthreads();
    }
    if (tid < nb) g_bsum[tid] = sh[tid] - v;
    if (tid == 127) g_rowptr[n] = sh[127];
}
__global__ void k_scan3(int n) {
    int i = blockIdx.x * blockDim.x + threadIdx.x;
    if (i >= n) return;
    int v = g_rowptr[i] + g_bsum[i >> 10];
    g_rowptr[i] = v;
    g_cursor[i] = v;
}
__global__ void k_fill(const int* __restrict__ src, const int* __restrict__ dst, int e) {
    int i = blockIdx.x * blockDim.x + threadIdx.x;
    if (i >= e) return;
    int d = dst[i];
    int pos = atomicAdd(&g_cursor[d], 1);
    g_csr_src[pos] = src[i];
}

// ======== GEMM: pre-split bf16 operands, PURE LDS+MMA mainloop ====================
// Output buffer selected by TB (0 -> g_ta, 1 -> g_tb). Rows [rbase, ...), guard M.
template<int DOUT, int FROM_X, int LAYER, int TB>
__global__ __launch_bounds__(256, 2)
void k_gemm_pre(const float* __restrict__ Ax, int rbase, int M) {
    constexpr int KP  = 64;
    constexpr int AKP = KP + 4;
    constexpr int WKP = DOUT + 8;
    constexpr int NT  = DOUT / 32;

    const uint32_t* Wh = (LAYER == 1) ? g_w1hi : (LAYER == 2) ? g_w2hi : g_w3hi;
    const uint32_t* Wl = (LAYER == 1) ? g_w1lo : (LAYER == 2) ? g_w2lo : g_w3lo;
    float* T = TB ? g_tb : g_ta;

    extern __shared__ uint32_t smu[];
    uint32_t* Ahi = smu;
    uint32_t* Alo = Ahi + 64 * AKP;
    uint32_t* Whi = Alo + 64 * AKP;
    uint32_t* Wlo = Whi + KP * WKP;

    int tid  = threadIdx.x;
    int row0 = rbase + blockIdx.x * 64;

    for (int i = tid; i < KP * (DOUT / 4); i += 256) {
        int kp = i / (DOUT / 4);
        int n4 = i % (DOUT / 4);
        uint4 h = ((const uint4*)Wh)[(size_t)kp * (DOUT / 4) + n4];
        uint4 l = ((const uint4*)Wl)[(size_t)kp * (DOUT / 4) + n4];
        *(uint4*)(Whi + kp * WKP + n4 * 4) = h;
        *(uint4*)(Wlo + kp * WKP + n4 * 4) = l;
    }
    for (int i = tid; i < 64 * 32; i += 256) {
        int r = i >> 5;
        int c = i & 31;
        int gr = row0 + r;
        uint2 h = make_uint2(0u, 0u), l = make_uint2(0u, 0u);
        if (FROM_X) {
            float4 v = make_float4(0.f, 0.f, 0.f, 0.f);
            if (gr < M) v = ((const float4*)Ax)[(size_t)gr * 32 + c];
            pack_split(make_float2(v.x, v.y), h.x, l.x);
            pack_split(make_float2(v.z, v.w), h.y, l.y);
        } else if (gr < M) {
            h = ((const uint2*)(g_ahi + (size_t)gr * 64))[c];
            l = ((const uint2*)(g_alo + (size_t)gr * 64))[c];
        }
        *(uint2*)(Ahi + r * AKP + c * 2) = h;
        *(uint2*)(Alo + r * AKP + c * 2) = l;
    }
    __syncthreads();

    int warp = tid >> 5, lane = tid & 31;
    int wm = warp & 1;
    int wn = warp >> 1;
    int g  = lane >> 2;
    int t  = lane & 3;
    int mbase = wm * 32;
    int nbase = wn * (DOUT / 4);

    float acc[2][NT][4];
#pragma unroll
    for (int i = 0; i < 2; i++)
#pragma unroll
        for (int j = 0; j < NT; j++)
#pragma unroll
            for (int q = 0; q < 4; q++) acc[i][j][q] = 0.f;

#pragma unroll 2
    for (int kb = 0; kb < KP; kb += 8) {
        uint32_t ahi[2][4], alo[2][4];
#pragma unroll
        for (int i = 0; i < 2; i++) {
            int base = (mbase + i * 16 + g) * AKP + kb + t;
            ahi[i][0] = Ahi[base];
            ahi[i][1] = Ahi[base + 8 * AKP];
            ahi[i][2] = Ahi[base + 4];
            ahi[i][3] = Ahi[base + 8 * AKP + 4];
            alo[i][0] = Alo[base];
            alo[i][1] = Alo[base + 8 * AKP];
            alo[i][2] = Alo[base + 4];
            alo[i][3] = Alo[base + 8 * AKP + 4];
        }
        uint32_t bhi[NT][2], blo[NT][2];
#pragma unroll
        for (int j = 0; j < NT; j++) {
            int col = nbase + j * 8 + g;
            int b0 = (kb + t) * WKP + col;
            int b1 = (kb + 4 + t) * WKP + col;
            bhi[j][0] = Whi[b0];
            bhi[j][1] = Whi[b1];
            blo[j][0] = Wlo[b0];
            blo[j][1] = Wlo[b1];
        }
#pragma unroll
        for (int i = 0; i < 2; i++)
#pragma unroll
            for (int j = 0; j < NT; j++) {
                mma_bf16(acc[i][j], ahi[i], bhi[j]);
                mma_bf16(acc[i][j], ahi[i], blo[j]);
                mma_bf16(acc[i][j], alo[i], bhi[j]);
            }
    }

#pragma unroll
    for (int i = 0; i < 2; i++) {
        int r_lo = row0 + mbase + i * 16 + g;
        int r_hi = r_lo + 8;
        float s_lo = (r_lo < M) ? dinv_of(r_lo) : 0.f;
        float s_hi = (r_hi < M) ? dinv_of(r_hi) : 0.f;
#pragma unroll
        for (int j = 0; j < NT; j++) {
            int col = nbase + j * 8 + 2 * t;
            if (r_lo < M)
                *(float2*)&T[(size_t)r_lo * DOUT + col] =
                    make_float2(s_lo * acc[i][j][0], s_lo * acc[i][j][1]);
            if (r_hi < M)
                *(float2*)&T[(size_t)r_hi * DOUT + col] =
                    make_float2(s_hi * acc[i][j][2], s_hi * acc[i][j][3]);
        }
    }
}

// ================= Aggregation over [wbase, wend), input buffer TB =================
template<int DOUT, int MODE, int TB>
__global__ void k_agg(const float* __restrict__ bias, float* __restrict__ out,
                      int wbase, int wend) {
    int w    = wbase + ((blockIdx.x * blockDim.x + threadIdx.x) >> 5);
    int lane = threadIdx.x & 31;
    if (w >= wend) return;
    constexpr int VF = DOUT / 32;
    const float* T = TB ? g_tb : g_ta;

    float acc[VF];
    {
        const float* p = T + (size_t)w * DOUT + lane * VF;
        if (VF == 4) { float4 v = *(const float4*)p; acc[0]=v.x; acc[1]=v.y; acc[2]=v.z; acc[3]=v.w; }
        else         { float2 v = *(const float2*)p; acc[0]=v.x; acc[1]=v.y; }
    }

    int beg = g_rowptr[w], end = g_rowptr[w + 1];
    for (int jb = beg; jb < end; jb += 32) {
        int myj = jb + lane;
        int ms  = (myj < end) ? g_csr_src[myj] : 0;
        int cnt = min(32, end - jb);
        int k = 0;
        for (; k + 4 <= cnt; k += 4) {
            int s0 = __shfl_sync(0xffffffffu, ms, k);
            int s1 = __shfl_sync(0xffffffffu, ms, k + 1);
            int s2 = __shfl_sync(0xffffffffu, ms, k + 2);
            int s3 = __shfl_sync(0xffffffffu, ms, k + 3);
            if (VF == 4) {
                float4 v0 = *(const float4*)(T + (size_t)s0 * DOUT + lane * 4);
                float4 v1 = *(const float4*)(T + (size_t)s1 * DOUT + lane * 4);
                float4 v2 = *(const float4*)(T + (size_t)s2 * DOUT + lane * 4);
                float4 v3 = *(const float4*)(T + (size_t)s3 * DOUT + lane * 4);
                acc[0] += (v0.x + v1.x) + (v2.x + v3.x);
                acc[1] += (v0.y + v1.y) + (v2.y + v3.y);
                acc[2] += (v0.z + v1.z) + (v2.z + v3.z);
                acc[3] += (v0.w + v1.w) + (v2.w + v3.w);
            } else {
                float2 v0 = *(const float2*)(T + (size_t)s0 * DOUT + lane * 2);
                float2 v1 = *(const float2*)(T + (size_t)s1 * DOUT + lane * 2);
                float2 v2 = *(const float2*)(T + (size_t)s2 * DOUT + lane * 2);
                float2 v3 = *(const float2*)(T + (size_t)s3 * DOUT + lane * 2);
                acc[0] += (v0.x + v1.x) + (v2.x + v3.x);
                acc[1] += (v0.y + v1.y) + (v2.y + v3.y);
            }
        }
        for (; k < cnt; k++) {
            int s = __shfl_sync(0xffffffffu, ms, k);
            if (VF == 4) {
                float4 v = *(const float4*)(T + (size_t)s * DOUT + lane * 4);
                acc[0] += v.x; acc[1] += v.y; acc[2] += v.z; acc[3] += v.w;
            } else {
                float2 v = *(const float2*)(T + (size_t)s * DOUT + lane * 2);
                acc[0] += v.x; acc[1] += v.y;
            }
        }
    }

    float di = dinv_of(w);
    if (MODE == 0) {
        float4 bb = ((const float4*)bias)[lane];
        float rx = fmaxf(fmaf(di, acc[0], bb.x), 0.f);
        float ry = fmaxf(fmaf(di, acc[1], bb.y), 0.f);
        float rz = fmaxf(fmaf(di, acc[2], bb.z), 0.f);
        float rw = fmaxf(fmaf(di, acc[3], bb.w), 0.f);
        uint32_t h0, l0, h1, l1;
        pack_split(make_float2(rx, ry), h0, l0);
        pack_split(make_float2(rz, rw), h1, l1);
        *(uint2*)(g_ahi + (size_t)w * 64 + lane * 2) = make_uint2(h0, h1);
        *(uint2*)(g_alo + (size_t)w * 64 + lane * 2) = make_uint2(l0, l1);
    } else {
        float2 bb = ((const float2*)bias)[lane];
        float vx = fmaf(di, acc[0], bb.x);
        float vy = fmaf(di, acc[1], bb.y);
        float m = fmaxf(vx, vy);
#pragma unroll
        for (int o = 16; o; o >>= 1) m = fmaxf(m, __shfl_xor_sync(0xffffffffu, m, o));
        float sum = expf(vx - m) + expf(vy - m);
#pragma unroll
        for (int o = 16; o; o >>= 1) sum += __shfl_xor_sync(0xffffffffu, sum, o);
        float lse = m + logf(sum);
        *(float2*)(out + (size_t)w * 64 + lane * 2) = make_float2(vx - lse, vy - lse);
    }
}

// ================= launch =================
extern "C" void kernel_launch(void* const* d_in, const int* in_sizes, int n_in,
                              void* d_out, int out_size) {
    const float* x   = (const float*)d_in[0];
    const int*   ei  = (const int*)d_in[1];     // int32 (JAX x64 disabled)
    const float* W1  = (const float*)d_in[2];
    const float* b1  = (const float*)d_in[3];
    const float* W2  = (const float*)d_in[4];
    const float* b2  = (const float*)d_in[5];
    const float* W3  = (const float*)d_in[6];
    const float* b3  = (const float*)d_in[7];
    float* out = (float*)d_out;

    int n = in_sizes[0] / FIN;
    int e = in_sizes[1] / 2;
    const int* srcp = ei;
    const int* dstp = ei + e;

    static cudaStream_t s2 = [] { cudaStream_t s; cudaStreamCreate(&s); return s; }();
    static cudaEvent_t evA = [] { cudaEvent_t v; cudaEventCreateWithFlags(&v, cudaEventDisableTiming); return v; }();
    static cudaEvent_t evB = [] { cudaEvent_t v; cudaEventCreateWithFlags(&v, cudaEventDisableTiming); return v; }();
    static cudaEvent_t evC = [] { cudaEvent_t v; cudaEventCreateWithFlags(&v, cudaEventDisableTiming); return v; }();
    static cudaEvent_t evE = [] { cudaEvent_t v; cudaEventCreateWithFlags(&v, cudaEventDisableTiming); return v; }();
    static cudaEvent_t evF = [] { cudaEvent_t v; cudaEventCreateWithFlags(&v, cudaEventDisableTiming); return v; }();
    static cudaEvent_t evH = [] { cudaEvent_t v; cudaEventCreateWithFlags(&v, cudaEventDisableTiming); return v; }();

    const int smemp128 = (2 * 64 * 68 + 2 * 64 * (HH   + 8)) * 4;   // ~102 KB -> 2 CTA/SM
    const int smemp64  = (2 * 64 * 68 + 2 * 64 * (OUTC + 8)) * 4;   // ~70 KB  -> 3 CTA/SM
    cudaFuncSetAttribute((const void*)k_gemm_pre<HH, 1, 1, 0>,
                         cudaFuncAttributeMaxDynamicSharedMemorySize, smemp128);
    cudaFuncSetAttribute((const void*)k_gemm_pre<HH, 0, 2, 1>,
                         cudaFuncAttributeMaxDynamicSharedMemorySize, smemp128);
    cudaFuncSetAttribute((const void*)k_gemm_pre<OUTC, 0, 3, 0>,
                         cudaFuncAttributeMaxDynamicSharedMemorySize, smemp64);

    int nb_scan = (n + 1023) >> 10;
    int n1 = ((n / 2) + 63) & ~63;            // H1 = [0, n1), H2 = [n1, n)
    if (n1 > n) n1 = n;
    int gb_full = (n + 63) / 64;
    int gb1 = n1 / 64;
    int gb2 = (n - n1 + 63) / 64;
    auto ablk = [](int cnt) { return (int)(((long long)cnt * 32 + 255) / 256); };

    // prologue: zero(+W splits), count; CSR scans on s2 overlapped with gemm1 (launch #4)
    k_zero <<<(n + 255) / 256, 256>>>(W1, W2, W3, n);                  // 1
    k_count<<<(e + 255) / 256, 256>>>(dstp, e);                        // 2
    cudaEventRecord(evA, 0);
    cudaStreamWaitEvent(s2, evA, 0);
    k_scan1<<<nb_scan, 1024, 0, s2>>>(n);                              // 3
    k_gemm_pre<HH, 1, 1, 0><<<gb_full, 256, smemp128>>>(x, 0, n);      // 4 <-- profiled, -> g_ta
    k_scan2<<<1, 128, 0, s2>>>(nb_scan, n);
    k_scan3<<<(n + 255) / 256, 256, 0, s2>>>(n);
    k_fill <<<(e + 255) / 256, 256, 0, s2>>>(srcp, dstp, e);
    cudaEventRecord(evB, s2);
    cudaStreamWaitEvent(0, evB, 0);

    // ---- layer boundary 1: agg1 (reads g_ta) || gemm2 (writes g_tb) ----
    k_agg<HH, 0, 0><<<ablk(n1), 256>>>(b1, nullptr, 0, n1);            // agg1.H1 (main)
    cudaEventRecord(evC, 0);
    k_gemm_pre<HH, 0, 2, 1><<<gb1, 256, smemp128>>>(nullptr, 0, n1);   // gemm2.H1 -> g_tb (main)
    cudaStreamWaitEvent(s2, evC, 0);
    k_agg<HH, 0, 0><<<ablk(n - n1), 256, 0, s2>>>(b1, nullptr, n1, n); // agg1.H2 (s2)
    k_gemm_pre<HH, 0, 2, 1><<<gb2, 256, smemp128, s2>>>(nullptr, n1, n); // gemm2.H2 (s2)
    cudaEventRecord(evE, s2);
    cudaStreamWaitEvent(0, evE, 0);

    // ---- layer boundary 2: agg2 (reads g_tb) || gemm3 (writes g_ta) ----
    k_agg<HH, 0, 1><<<ablk(n1), 256>>>(b2, nullptr, 0, n1);            // agg2.H1 (main)
    cudaEventRecord(evF, 0);
    k_gemm_pre<OUTC, 0, 3, 0><<<gb1, 256, smemp64>>>(nullptr, 0, n1);  // gemm3.H1 -> g_ta (main)
    cudaStreamWaitEvent(s2, evF, 0);
    k_agg<HH, 0, 1><<<ablk(n - n1), 256, 0, s2>>>(b2, nullptr, n1, n); // agg2.H2 (s2)
    k_gemm_pre<OUTC, 0, 3, 0><<<gb2, 256, smemp64, s2>>>(nullptr, n1, n); // gemm3.H2 (s2)
    cudaEventRecord(evH, s2);
    cudaStreamWaitEvent(0, evH, 0);

    // final aggregate + log_softmax (reads g_ta)
    k_agg<OUTC, 1, 0><<<ablk(n), 256>>>(b3, out, 0, n);
}